// round 9
// baseline (speedup 1.0000x reference)
#include <cuda_runtime.h>
#include <math.h>

#define NN 100000
#define NE 1600000
#define SCAN_G 196   // ceil(100000/512)

// ---------------- scratch (__device__ globals; zero-init at module load) ----
__device__ __align__(16) int   g_rowptr[NN + 1];
__device__ __align__(16) int   g_cursor[NN];      // zeroed by final_kernel tail
__device__ __align__(16) int   g_csr[NE];
__device__ __align__(16) float g_pq[NN * 32];     // per node: [p2(16) | q2(16)]
__device__ unsigned long long  g_state[SCAN_G];   // zeroed by final_kernel tail
__device__ int                 g_ticket;          // zeroed by final_kernel tail

// ---------------- packed f32x2 helpers ----------------
__device__ __forceinline__ unsigned long long bcast2(float a) {
    unsigned long long r;
    asm("mov.b64 %0,{%1,%1};" : "=l"(r) : "f"(a));
    return r;
}
__device__ __forceinline__ float2 unpk2(unsigned long long v) {
    float2 r;
    asm("mov.b64 {%0,%1},%2;" : "=f"(r.x), "=f"(r.y) : "l"(v));
    return r;
}
#define FMA2(d, a, b, c) asm("fma.rn.f32x2 %0,%1,%2,%3;" : "=l"(d) : "l"(a), "l"(b), "l"(c))
#define ADD2(d, a, b)    asm("add.rn.f32x2 %0,%1,%2;"    : "=l"(d) : "l"(a), "l"(b))
#define MUL2(d, a, b)    asm("mul.rn.f32x2 %0,%1,%2;"    : "=l"(d) : "l"(a), "l"(b))

// ---------------------------------------------------------------------------
// CSR build
// ---------------------------------------------------------------------------
__global__ void k_hist(const int* __restrict__ ei) {
    int e = blockIdx.x * blockDim.x + threadIdx.x;
    if (e < NE) atomicAdd(&g_cursor[__ldg(ei + NE + e)], 1);
}

__device__ __forceinline__ int warp_incl_scan(int v) {
    int lane = threadIdx.x & 31;
#pragma unroll
    for (int d = 1; d < 32; d <<= 1) {
        int t = __shfl_up_sync(0xFFFFFFFFu, v, d);
        if (lane >= d) v += t;
    }
    return v;
}

__global__ void __launch_bounds__(512) k_scan() {
    __shared__ int ws[16];
    __shared__ int sbid;
    __shared__ int s_prefix;
    int tid = threadIdx.x;
    if (tid == 0) { sbid = atomicAdd(&g_ticket, 1); s_prefix = 0; }
    __syncthreads();
    int bid = sbid;
    int g = bid * 512 + tid;
    int v = (g < NN) ? g_cursor[g] : 0;
    int inc = warp_incl_scan(v);
    int wid = tid >> 5, lane = tid & 31;
    if (lane == 31) ws[wid] = inc;
    __syncthreads();
    if (wid == 0) {
        int t = (lane < 16) ? ws[lane] : 0;
        t = warp_incl_scan(t);
        if (lane < 16) ws[lane] = t;
    }
    __syncthreads();
    int off = (wid > 0) ? ws[wid - 1] : 0;
    int linc = inc + off;

    if (tid == 511) {
        unsigned long long pk = ((unsigned long long)linc << 2) | (bid == 0 ? 2ull : 1ull);
        __threadfence();
        atomicExch(&g_state[bid], pk);
    }
    if (bid > 0 && tid == 0) {
        long long run = 0;
        int p = bid - 1;
        while (true) {
            unsigned long long st;
            do { st = *((volatile unsigned long long*)&g_state[p]); } while ((st & 3ull) == 0);
            run += (long long)(st >> 2);
            if ((st & 3ull) == 2ull) break;
            p--;
        }
        s_prefix = (int)run;
    }
    __syncthreads();
    int pref = s_prefix;
    if (bid > 0 && tid == 511) {
        unsigned long long pk = ((unsigned long long)(pref + linc) << 2) | 2ull;
        __threadfence();
        atomicExch(&g_state[bid], pk);
    }
    int excl = pref + (linc - v);
    if (g < NN) { g_rowptr[g] = excl; g_cursor[g] = excl; }
    if (g == NN) g_rowptr[NN] = excl;
}

__global__ void k_fill(const int* __restrict__ ei) {
    int e = blockIdx.x * blockDim.x + threadIdx.x;
    if (e < NE) {
        int src = __ldg(ei + e);
        int dst = __ldg(ei + NE + e);
        int pos = atomicAdd(&g_cursor[dst], 1);
        g_csr[pos] = src;
    }
}

// ---------------------------------------------------------------------------
// Dense (fused gather): 128 threads, 128 nodes/block.
//  Phase G: mean of x over in-neighbors -> sM[64][TSD] smem (16 lanes/node,
//           LDG.128/lane, unroll x8 for MLP at 2 warps/SMSP).
//  Phase A: h1 = relu(mean@W1l + x@W1r + b1) -> regs (2 nodes x 32 cols/thread)
//  Phase B: [p2|q2] = h1@[W2l|W2r] + [0|b2] via partials + shfl_xor(1) reduce.
// ---------------------------------------------------------------------------
#define TSD 129
#define DSM_FLOATS (4096 + 4096 + 2048 + 64 * TSD + 16 * TSD + 32 + 64)

__global__ void __launch_bounds__(128) dense_kernel(
    const float* __restrict__ x,
    const float* __restrict__ W1l, const float* __restrict__ W1r,
    const float* __restrict__ b1,
    const float* __restrict__ W2l, const float* __restrict__ W2r,
    const float* __restrict__ b2)
{
    extern __shared__ float smem[];
    float* sWl = smem;                 // [k*64 + j]
    float* sWr = sWl + 4096;
    float* sW2 = sWr + 4096;           // [k*32 + j]
    float* sM  = sW2 + 2048;           // [k*TSD + node_local], all 64 k
    float* sX  = sM + 64 * TSD;        // [k*TSD + node_local], 16 k staged
    float* sB2 = sX + 16 * TSD;        // 32
    float* sB1 = sB2 + 32;             // 64

    int tid = threadIdx.x;
    int nbase = blockIdx.x * 128;

    for (int i = tid; i < 1024; i += 128) {
        ((float4*)sWl)[i] = ((const float4*)W1l)[i];
        ((float4*)sWr)[i] = ((const float4*)W1r)[i];
    }
    for (int i = tid; i < 1024; i += 128) {
        int k = i >> 4, j = i & 15;
        sW2[k * 32 + j]      = W2l[i];
        sW2[k * 32 + 16 + j] = W2r[i];
    }
    if (tid < 16) { sB2[tid] = 0.f; sB2[16 + tid] = b2[tid]; }
    if (tid < 64) sB1[tid] = b1[tid];

    // ---- Phase G: gather means into sM ----
    {
        int gl = tid >> 4;            // node slot 0..7 per pass
        int c  = tid & 15;            // 16B chunk within the 256B row
        const ulonglong2* x2 = (const ulonglong2*)x;
        for (int pass = 0; pass < 16; pass++) {
            int nl = pass * 8 + gl;
            int node = nbase + nl;
            unsigned long long a0 = 0ull, a1 = 0ull;
            if (node < NN) {
                int s = __ldg(g_rowptr + node);
                int e = __ldg(g_rowptr + node + 1);
                int i = s;
                for (; i + 8 <= e; i += 8) {
                    int sv[8];
#pragma unroll
                    for (int u = 0; u < 8; u++) sv[u] = __ldg(g_csr + i + u);
                    ulonglong2 vv[8];
#pragma unroll
                    for (int u = 0; u < 8; u++) vv[u] = __ldg(x2 + (size_t)sv[u] * 16 + c);
#pragma unroll
                    for (int u = 0; u < 8; u++) {
                        ADD2(a0, a0, vv[u].x);
                        ADD2(a1, a1, vv[u].y);
                    }
                }
                for (; i < e; i++) {
                    int s0 = __ldg(g_csr + i);
                    ulonglong2 v0 = __ldg(x2 + (size_t)s0 * 16 + c);
                    ADD2(a0, a0, v0.x); ADD2(a1, a1, v0.y);
                }
                unsigned long long I = bcast2(1.f / fmaxf((float)(e - s), 1.f));
                MUL2(a0, a0, I);
                MUL2(a1, a1, I);
            }
            float2 u0 = unpk2(a0), u1 = unpk2(a1);
            sM[(4 * c + 0) * TSD + nl] = u0.x;
            sM[(4 * c + 1) * TSD + nl] = u0.y;
            sM[(4 * c + 2) * TSD + nl] = u1.x;
            sM[(4 * c + 3) * TSD + nl] = u1.y;
        }
    }

    // ---- Phase A ----
    int cs = tid & 1;
    int np = tid >> 1;
    int nl0 = np * 2, nl1 = nl0 + 1;
    int jb = cs * 32;

    unsigned long long accA[32];
#pragma unroll
    for (int j = 0; j < 32; j++) accA[j] = 0ull;

    const float4* x4 = (const float4*)x;
    float4 z4 = make_float4(0.f, 0.f, 0.f, 0.f);

    for (int kb = 0; kb < 4; kb++) {
        __syncthreads();   // (kb=0: also fences phase G writes to sM)
        for (int i = tid; i < 512; i += 128) {
            int nn = i >> 2, cc = i & 3;
            int gn = nbase + nn;
            float4 vx = (gn < NN) ? __ldg(x4 + (size_t)gn * 16 + kb * 4 + cc) : z4;
            int kr = cc * 4;
            sX[(kr + 0) * TSD + nn] = vx.x;
            sX[(kr + 1) * TSD + nn] = vx.y;
            sX[(kr + 2) * TSD + nn] = vx.z;
            sX[(kr + 3) * TSD + nn] = vx.w;
        }
        __syncthreads();
#pragma unroll
        for (int k = 0; k < 16; k++) {
            int kg = kb * 16 + k;
            unsigned long long A0 = bcast2(sM[kg * TSD + nl0]);
            unsigned long long A1 = bcast2(sM[kg * TSD + nl1]);
            unsigned long long X0 = bcast2(sX[k * TSD + nl0]);
            unsigned long long X1 = bcast2(sX[k * TSD + nl1]);
            const ulonglong2* wl = (const ulonglong2*)(sWl + kg * 64 + jb);
            const ulonglong2* wr = (const ulonglong2*)(sWr + kg * 64 + jb);
#pragma unroll
            for (int jh = 0; jh < 8; jh++) {
                ulonglong2 wwl = wl[jh];
                ulonglong2 wwr = wr[jh];
                FMA2(accA[2 * jh],          A0, wwl.x, accA[2 * jh]);
                FMA2(accA[2 * jh + 1],      A0, wwl.y, accA[2 * jh + 1]);
                FMA2(accA[16 + 2 * jh],     A1, wwl.x, accA[16 + 2 * jh]);
                FMA2(accA[16 + 2 * jh + 1], A1, wwl.y, accA[16 + 2 * jh + 1]);
                FMA2(accA[2 * jh],          X0, wwr.x, accA[2 * jh]);
                FMA2(accA[2 * jh + 1],      X0, wwr.y, accA[2 * jh + 1]);
                FMA2(accA[16 + 2 * jh],     X1, wwr.x, accA[16 + 2 * jh]);
                FMA2(accA[16 + 2 * jh + 1], X1, wwr.y, accA[16 + 2 * jh + 1]);
            }
        }
    }

    float h1s[2][32];
#pragma unroll
    for (int p = 0; p < 16; p++) {
        float b0 = sB1[jb + 2 * p];
        float b1v = sB1[jb + 2 * p + 1];
        float2 u0 = unpk2(accA[p]);
        float2 u1 = unpk2(accA[16 + p]);
        h1s[0][2 * p]     = fmaxf(u0.x + b0,  0.f);
        h1s[0][2 * p + 1] = fmaxf(u0.y + b1v, 0.f);
        h1s[1][2 * p]     = fmaxf(u1.x + b0,  0.f);
        h1s[1][2 * p + 1] = fmaxf(u1.y + b1v, 0.f);
    }

    // ---- Phase B ----
    unsigned long long accB[32];
#pragma unroll
    for (int j = 0; j < 32; j++) accB[j] = 0ull;
#pragma unroll
    for (int kk = 0; kk < 32; kk++) {
        int k = jb + kk;
        const ulonglong2* w2 = (const ulonglong2*)(sW2 + k * 32);
        unsigned long long H0 = bcast2(h1s[0][kk]);
        unsigned long long H1 = bcast2(h1s[1][kk]);
#pragma unroll
        for (int jh = 0; jh < 8; jh++) {
            ulonglong2 w = w2[jh];
            FMA2(accB[2 * jh],          H0, w.x, accB[2 * jh]);
            FMA2(accB[2 * jh + 1],      H0, w.y, accB[2 * jh + 1]);
            FMA2(accB[16 + 2 * jh],     H1, w.x, accB[16 + 2 * jh]);
            FMA2(accB[16 + 2 * jh + 1], H1, w.y, accB[16 + 2 * jh + 1]);
        }
    }
#pragma unroll
    for (int j = 0; j < 32; j++) {
        unsigned long long o = __shfl_xor_sync(0xFFFFFFFFu, accB[j], 1);
        ADD2(accB[j], accB[j], o);
    }
    int node = nbase + (cs ? nl1 : nl0);
    const unsigned long long* mine = accB + cs * 16;
    if (node < NN) {
        float o[32];
#pragma unroll
        for (int p = 0; p < 16; p++) {
            float2 u = unpk2(mine[p]);
            o[2 * p]     = u.x + sB2[2 * p];
            o[2 * p + 1] = u.y + sB2[2 * p + 1];
        }
        float4* dst = (float4*)(g_pq + (size_t)node * 32);
#pragma unroll
        for (int q = 0; q < 8; q++) dst[q] = *(float4*)(o + 4 * q);
    }
}

// ---------------------------------------------------------------------------
// Final: gather mean(p2) + q2 -> log_softmax -> out, then reset scratch state
// for the next graph replay (deterministic: every completed call re-zeroes).
// ---------------------------------------------------------------------------
__global__ void __launch_bounds__(256) final_kernel(float* __restrict__ out) {
    int tid = threadIdx.x;
    int node = blockIdx.x * 64 + (tid >> 2);
    int c = tid & 3;
    bool nv = node < NN;
    int s = 0, e = 0;
    if (nv) { s = __ldg(g_rowptr + node); e = __ldg(g_rowptr + node + 1); }
    unsigned long long a0 = 0ull, a1 = 0ull;
    const ulonglong2* pq2 = (const ulonglong2*)g_pq;
    int i = s;
    for (; i + 4 <= e; i += 4) {
        int s0 = __ldg(g_csr + i);
        int s1 = __ldg(g_csr + i + 1);
        int s2 = __ldg(g_csr + i + 2);
        int s3 = __ldg(g_csr + i + 3);
        ulonglong2 v0 = __ldg(pq2 + (size_t)s0 * 8 + c);
        ulonglong2 v1 = __ldg(pq2 + (size_t)s1 * 8 + c);
        ulonglong2 v2 = __ldg(pq2 + (size_t)s2 * 8 + c);
        ulonglong2 v3 = __ldg(pq2 + (size_t)s3 * 8 + c);
        ADD2(a0, a0, v0.x); ADD2(a1, a1, v0.y);
        ADD2(a0, a0, v1.x); ADD2(a1, a1, v1.y);
        ADD2(a0, a0, v2.x); ADD2(a1, a1, v2.y);
        ADD2(a0, a0, v3.x); ADD2(a1, a1, v3.y);
    }
    for (; i < e; i++) {
        int s0 = __ldg(g_csr + i);
        ulonglong2 v0 = __ldg(pq2 + (size_t)s0 * 8 + c);
        ADD2(a0, a0, v0.x); ADD2(a1, a1, v0.y);
    }
    float invd = 1.f / fmaxf((float)(e - s), 1.f);
    float2 u0 = unpk2(a0), u1 = unpk2(a1);
    float4 q = nv ? __ldg((const float4*)g_pq + (size_t)node * 8 + 4 + c)
                  : make_float4(0.f, 0.f, 0.f, 0.f);
    float v[4];
    v[0] = u0.x * invd + q.x;
    v[1] = u0.y * invd + q.y;
    v[2] = u1.x * invd + q.z;
    v[3] = u1.y * invd + q.w;

    float m = fmaxf(fmaxf(v[0], v[1]), fmaxf(v[2], v[3]));
    m = fmaxf(m, __shfl_xor_sync(0xFFFFFFFFu, m, 1));
    m = fmaxf(m, __shfl_xor_sync(0xFFFFFFFFu, m, 2));
    float sum = expf(v[0] - m) + expf(v[1] - m) + expf(v[2] - m) + expf(v[3] - m);
    sum += __shfl_xor_sync(0xFFFFFFFFu, sum, 1);
    sum += __shfl_xor_sync(0xFFFFFFFFu, sum, 2);
    float lse = m + logf(sum);

    if (nv) {
        float4 o;
        o.x = v[0] - lse; o.y = v[1] - lse; o.z = v[2] - lse; o.w = v[3] - lse;
        ((float4*)out)[(size_t)node * 4 + c] = o;
    }

    // ---- reset scratch for the next replay ----
    int gid = blockIdx.x * 256 + tid;
    if (gid < NN) g_cursor[gid] = 0;
    if (gid < SCAN_G) g_state[gid] = 0ull;
    if (gid == 0) g_ticket = 0;
}

// ---------------------------------------------------------------------------
extern "C" void kernel_launch(void* const* d_in, const int* in_sizes, int n_in,
                              void* d_out, int out_size) {
    const float* x   = (const float*)d_in[0];
    const int*   ei  = (const int*)d_in[1];
    const float* W1l = (const float*)d_in[2];
    const float* W1r = (const float*)d_in[3];
    const float* b1  = (const float*)d_in[4];
    const float* W2l = (const float*)d_in[5];
    const float* W2r = (const float*)d_in[6];
    const float* b2  = (const float*)d_in[7];
    float* out = (float*)d_out;

    k_hist<<<(NE + 255) / 256, 256>>>(ei);        // our launch 0
    k_scan<<<SCAN_G, 512>>>();                    // 1
    k_fill<<<(NE + 255) / 256, 256>>>(ei);        // 2

    cudaFuncSetAttribute(dense_kernel,
                         cudaFuncAttributeMaxDynamicSharedMemorySize,
                         DSM_FLOATS * sizeof(float));
    dense_kernel<<<(NN + 127) / 128, 128, DSM_FLOATS * sizeof(float)>>>(
        x, W1l, W1r, b1, W2l, W2r, b2);           // 3  <- ncu profiles this

    final_kernel<<<(NN + 63) / 64, 256>>>(out);   // 4
}

// round 10
// speedup vs baseline: 1.1754x; 1.1754x over previous
#include <cuda_runtime.h>
#include <math.h>

#define NN 100000
#define NE 1600000
#define SCAN_G 196   // ceil(100000/512)
#define FG_BLOCKS 592   // 4 blocks/SM on 148 SMs: guaranteed co-resident

// ---------------- scratch (__device__ globals; zero-init at module load) ----
__device__ __align__(16) int   g_rowptr[NN + 1];
__device__ __align__(16) int   g_cursor[NN];      // zeroed by final_kernel tail
__device__ __align__(16) int   g_csr[NE];
__device__ __align__(16) float g_mean[NN * 64];   // mean of x over in-neighbors
__device__ __align__(16) float g_pq[NN * 32];     // per node: [p2(16) | q2(16)]
__device__ unsigned long long  g_state[SCAN_G];   // zeroed by final_kernel tail
__device__ int                 g_ticket;          // zeroed by final_kernel tail
__device__ int                 g_bar_cnt;         // self-resetting
__device__ volatile int        g_bar_phase;       // monotonically increasing

// ---------------- packed f32x2 helpers ----------------
__device__ __forceinline__ unsigned long long bcast2(float a) {
    unsigned long long r;
    asm("mov.b64 %0,{%1,%1};" : "=l"(r) : "f"(a));
    return r;
}
__device__ __forceinline__ float2 unpk2(unsigned long long v) {
    float2 r;
    asm("mov.b64 {%0,%1},%2;" : "=f"(r.x), "=f"(r.y) : "l"(v));
    return r;
}
#define FMA2(d, a, b, c) asm("fma.rn.f32x2 %0,%1,%2,%3;" : "=l"(d) : "l"(a), "l"(b), "l"(c))
#define ADD2(d, a, b)    asm("add.rn.f32x2 %0,%1,%2;"    : "=l"(d) : "l"(a), "l"(b))
#define MUL2(d, a, b)    asm("mul.rn.f32x2 %0,%1,%2;"    : "=l"(d) : "l"(a), "l"(b))

// ---------------- software grid barrier (blocks all co-resident) ----------
__device__ __forceinline__ void grid_sync(int nb) {
    __syncthreads();
    if (threadIdx.x == 0) {
        int ph = g_bar_phase;
        __threadfence();
        if (atomicAdd(&g_bar_cnt, 1) == nb - 1) {
            g_bar_cnt = 0;
            __threadfence();
            g_bar_phase = ph + 1;
        } else {
            while (g_bar_phase == ph) { }
        }
    }
    __syncthreads();
}

// ---------------------------------------------------------------------------
// CSR build: histogram + single-pass lookback scan
// ---------------------------------------------------------------------------
__global__ void k_hist(const int* __restrict__ ei) {
    int e = blockIdx.x * blockDim.x + threadIdx.x;
    if (e < NE) atomicAdd(&g_cursor[__ldg(ei + NE + e)], 1);
}

__device__ __forceinline__ int warp_incl_scan(int v) {
    int lane = threadIdx.x & 31;
#pragma unroll
    for (int d = 1; d < 32; d <<= 1) {
        int t = __shfl_up_sync(0xFFFFFFFFu, v, d);
        if (lane >= d) v += t;
    }
    return v;
}

__global__ void __launch_bounds__(512) k_scan() {
    __shared__ int ws[16];
    __shared__ int sbid;
    __shared__ int s_prefix;
    int tid = threadIdx.x;
    if (tid == 0) { sbid = atomicAdd(&g_ticket, 1); s_prefix = 0; }
    __syncthreads();
    int bid = sbid;
    int g = bid * 512 + tid;
    int v = (g < NN) ? g_cursor[g] : 0;
    int inc = warp_incl_scan(v);
    int wid = tid >> 5, lane = tid & 31;
    if (lane == 31) ws[wid] = inc;
    __syncthreads();
    if (wid == 0) {
        int t = (lane < 16) ? ws[lane] : 0;
        t = warp_incl_scan(t);
        if (lane < 16) ws[lane] = t;
    }
    __syncthreads();
    int off = (wid > 0) ? ws[wid - 1] : 0;
    int linc = inc + off;

    if (tid == 511) {
        unsigned long long pk = ((unsigned long long)linc << 2) | (bid == 0 ? 2ull : 1ull);
        __threadfence();
        atomicExch(&g_state[bid], pk);
    }
    if (bid > 0 && tid == 0) {
        long long run = 0;
        int p = bid - 1;
        while (true) {
            unsigned long long st;
            do { st = *((volatile unsigned long long*)&g_state[p]); } while ((st & 3ull) == 0);
            run += (long long)(st >> 2);
            if ((st & 3ull) == 2ull) break;
            p--;
        }
        s_prefix = (int)run;
    }
    __syncthreads();
    int pref = s_prefix;
    if (bid > 0 && tid == 511) {
        unsigned long long pk = ((unsigned long long)(pref + linc) << 2) | 2ull;
        __threadfence();
        atomicExch(&g_state[bid], pk);
    }
    int excl = pref + (linc - v);
    if (g < NN) { g_rowptr[g] = excl; g_cursor[g] = excl; }
    if (g == NN) g_rowptr[NN] = excl;
}

// ---------------------------------------------------------------------------
// Fused fill + gather: fill CSR buckets, grid-sync, then gather mean(x).
// 592 blocks x 256 thr (4/SM, all resident -> barrier is safe).
// ---------------------------------------------------------------------------
__global__ void __launch_bounds__(256) k_fillgather(const int* __restrict__ ei,
                                                   const float* __restrict__ x) {
    int gtid = blockIdx.x * 256 + threadIdx.x;
    int nthr = FG_BLOCKS * 256;

    // ---- phase 1: fill ----
    for (int e = gtid; e < NE; e += nthr) {
        int src = __ldg(ei + e);
        int dst = __ldg(ei + NE + e);
        int pos = atomicAdd(&g_cursor[dst], 1);
        g_csr[pos] = src;
    }

    grid_sync(FG_BLOCKS);   // csr fully built + visible

    // ---- phase 2: gather (16 lanes/node, LDG.128/lane, unroll x4) ----
    const ulonglong2* x2 = (const ulonglong2*)x;
    const long long total = (long long)NN * 16;
    for (long long it = gtid; it < total; it += nthr) {
        int node = (int)(it >> 4);
        int c = (int)(it & 15);
        int s = __ldg(g_rowptr + node);
        int e = __ldg(g_rowptr + node + 1);
        unsigned long long a0 = 0ull, a1 = 0ull;
        int i = s;
        for (; i + 4 <= e; i += 4) {
            int s0 = __ldg(g_csr + i);
            int s1 = __ldg(g_csr + i + 1);
            int s2 = __ldg(g_csr + i + 2);
            int s3 = __ldg(g_csr + i + 3);
            ulonglong2 v0 = __ldg(x2 + (size_t)s0 * 16 + c);
            ulonglong2 v1 = __ldg(x2 + (size_t)s1 * 16 + c);
            ulonglong2 v2 = __ldg(x2 + (size_t)s2 * 16 + c);
            ulonglong2 v3 = __ldg(x2 + (size_t)s3 * 16 + c);
            ADD2(a0, a0, v0.x); ADD2(a1, a1, v0.y);
            ADD2(a0, a0, v1.x); ADD2(a1, a1, v1.y);
            ADD2(a0, a0, v2.x); ADD2(a1, a1, v2.y);
            ADD2(a0, a0, v3.x); ADD2(a1, a1, v3.y);
        }
        for (; i < e; i++) {
            int s0 = __ldg(g_csr + i);
            ulonglong2 v0 = __ldg(x2 + (size_t)s0 * 16 + c);
            ADD2(a0, a0, v0.x); ADD2(a1, a1, v0.y);
        }
        unsigned long long I = bcast2(1.f / fmaxf((float)(e - s), 1.f));
        ulonglong2 o;
        MUL2(o.x, a0, I);
        MUL2(o.y, a1, I);
        ((ulonglong2*)g_mean)[(size_t)node * 16 + c] = o;
    }
}

// ---------------------------------------------------------------------------
// Dense: 128 threads, 128 nodes/block. Thread = 2 nodes x 32 cols (col half).
// ---------------------------------------------------------------------------
#define TSD 129
#define DSM_FLOATS (4096 + 4096 + 2048 + 2 * 16 * TSD + 32 + 64)

__global__ void __launch_bounds__(128, 3) dense_kernel(
    const float* __restrict__ x,
    const float* __restrict__ W1l, const float* __restrict__ W1r,
    const float* __restrict__ b1,
    const float* __restrict__ W2l, const float* __restrict__ W2r,
    const float* __restrict__ b2)
{
    extern __shared__ float smem[];
    float* sWl = smem;                 // [k*64 + j]
    float* sWr = sWl + 4096;
    float* sW2 = sWr + 4096;           // [k*32 + j]
    float* sA  = sW2 + 2048;           // [k*TSD + node_local], 16 k
    float* sX  = sA + 16 * TSD;
    float* sB2 = sX + 16 * TSD;        // 32
    float* sB1 = sB2 + 32;             // 64

    int tid = threadIdx.x;
    int nbase = blockIdx.x * 128;

    for (int i = tid; i < 1024; i += 128) {
        ((float4*)sWl)[i] = ((const float4*)W1l)[i];
        ((float4*)sWr)[i] = ((const float4*)W1r)[i];
    }
    for (int i = tid; i < 1024; i += 128) {
        int k = i >> 4, j = i & 15;
        sW2[k * 32 + j]      = W2l[i];
        sW2[k * 32 + 16 + j] = W2r[i];
    }
    if (tid < 16) { sB2[tid] = 0.f; sB2[16 + tid] = b2[tid]; }
    if (tid < 64) sB1[tid] = b1[tid];

    int cs = tid & 1;
    int np = tid >> 1;
    int nl0 = np * 2, nl1 = nl0 + 1;
    int jb = cs * 32;

    unsigned long long accA[32];
#pragma unroll
    for (int j = 0; j < 32; j++) accA[j] = 0ull;

    const float4* x4 = (const float4*)x;
    const float4* m4 = (const float4*)g_mean;
    float4 z4 = make_float4(0.f, 0.f, 0.f, 0.f);

    for (int kb = 0; kb < 4; kb++) {
        __syncthreads();
        for (int i = tid; i < 512; i += 128) {
            int nn = i >> 2, cc = i & 3;
            int gn = nbase + nn;
            float4 va = (gn < NN) ? __ldg(m4 + (size_t)gn * 16 + kb * 4 + cc) : z4;
            float4 vx = (gn < NN) ? __ldg(x4 + (size_t)gn * 16 + kb * 4 + cc) : z4;
            int kr = cc * 4;
            sA[(kr + 0) * TSD + nn] = va.x;
            sA[(kr + 1) * TSD + nn] = va.y;
            sA[(kr + 2) * TSD + nn] = va.z;
            sA[(kr + 3) * TSD + nn] = va.w;
            sX[(kr + 0) * TSD + nn] = vx.x;
            sX[(kr + 1) * TSD + nn] = vx.y;
            sX[(kr + 2) * TSD + nn] = vx.z;
            sX[(kr + 3) * TSD + nn] = vx.w;
        }
        __syncthreads();
#pragma unroll
        for (int k = 0; k < 16; k++) {
            int kg = kb * 16 + k;
            unsigned long long A0 = bcast2(sA[k * TSD + nl0]);
            unsigned long long A1 = bcast2(sA[k * TSD + nl1]);
            unsigned long long X0 = bcast2(sX[k * TSD + nl0]);
            unsigned long long X1 = bcast2(sX[k * TSD + nl1]);
            const ulonglong2* wl = (const ulonglong2*)(sWl + kg * 64 + jb);
            const ulonglong2* wr = (const ulonglong2*)(sWr + kg * 64 + jb);
#pragma unroll
            for (int jh = 0; jh < 8; jh++) {
                ulonglong2 wwl = wl[jh];
                ulonglong2 wwr = wr[jh];
                FMA2(accA[2 * jh],          A0, wwl.x, accA[2 * jh]);
                FMA2(accA[2 * jh + 1],      A0, wwl.y, accA[2 * jh + 1]);
                FMA2(accA[16 + 2 * jh],     A1, wwl.x, accA[16 + 2 * jh]);
                FMA2(accA[16 + 2 * jh + 1], A1, wwl.y, accA[16 + 2 * jh + 1]);
                FMA2(accA[2 * jh],          X0, wwr.x, accA[2 * jh]);
                FMA2(accA[2 * jh + 1],      X0, wwr.y, accA[2 * jh + 1]);
                FMA2(accA[16 + 2 * jh],     X1, wwr.x, accA[16 + 2 * jh]);
                FMA2(accA[16 + 2 * jh + 1], X1, wwr.y, accA[16 + 2 * jh + 1]);
            }
        }
    }

    float h1s[2][32];
#pragma unroll
    for (int p = 0; p < 16; p++) {
        float b0 = sB1[jb + 2 * p];
        float b1v = sB1[jb + 2 * p + 1];
        float2 u0 = unpk2(accA[p]);
        float2 u1 = unpk2(accA[16 + p]);
        h1s[0][2 * p]     = fmaxf(u0.x + b0,  0.f);
        h1s[0][2 * p + 1] = fmaxf(u0.y + b1v, 0.f);
        h1s[1][2 * p]     = fmaxf(u1.x + b0,  0.f);
        h1s[1][2 * p + 1] = fmaxf(u1.y + b1v, 0.f);
    }

    unsigned long long accB[32];
#pragma unroll
    for (int j = 0; j < 32; j++) accB[j] = 0ull;
#pragma unroll
    for (int kk = 0; kk < 32; kk++) {
        int k = jb + kk;
        const ulonglong2* w2 = (const ulonglong2*)(sW2 + k * 32);
        unsigned long long H0 = bcast2(h1s[0][kk]);
        unsigned long long H1 = bcast2(h1s[1][kk]);
#pragma unroll
        for (int jh = 0; jh < 8; jh++) {
            ulonglong2 w = w2[jh];
            FMA2(accB[2 * jh],          H0, w.x, accB[2 * jh]);
            FMA2(accB[2 * jh + 1],      H0, w.y, accB[2 * jh + 1]);
            FMA2(accB[16 + 2 * jh],     H1, w.x, accB[16 + 2 * jh]);
            FMA2(accB[16 + 2 * jh + 1], H1, w.y, accB[16 + 2 * jh + 1]);
        }
    }
#pragma unroll
    for (int j = 0; j < 32; j++) {
        unsigned long long o = __shfl_xor_sync(0xFFFFFFFFu, accB[j], 1);
        ADD2(accB[j], accB[j], o);
    }
    int node = nbase + (cs ? nl1 : nl0);
    const unsigned long long* mine = accB + cs * 16;
    if (node < NN) {
        float o[32];
#pragma unroll
        for (int p = 0; p < 16; p++) {
            float2 u = unpk2(mine[p]);
            o[2 * p]     = u.x + sB2[2 * p];
            o[2 * p + 1] = u.y + sB2[2 * p + 1];
        }
        float4* dst = (float4*)(g_pq + (size_t)node * 32);
#pragma unroll
        for (int q = 0; q < 8; q++) dst[q] = *(float4*)(o + 4 * q);
    }
}

// ---------------------------------------------------------------------------
// Final: gather mean(p2) + q2 -> log_softmax -> out, then reset scratch state.
// ---------------------------------------------------------------------------
__global__ void __launch_bounds__(256) final_kernel(float* __restrict__ out) {
    int tid = threadIdx.x;
    int node = blockIdx.x * 64 + (tid >> 2);
    int c = tid & 3;
    bool nv = node < NN;
    int s = 0, e = 0;
    if (nv) { s = __ldg(g_rowptr + node); e = __ldg(g_rowptr + node + 1); }
    unsigned long long a0 = 0ull, a1 = 0ull;
    const ulonglong2* pq2 = (const ulonglong2*)g_pq;
    int i = s;
    for (; i + 4 <= e; i += 4) {
        int s0 = __ldg(g_csr + i);
        int s1 = __ldg(g_csr + i + 1);
        int s2 = __ldg(g_csr + i + 2);
        int s3 = __ldg(g_csr + i + 3);
        ulonglong2 v0 = __ldg(pq2 + (size_t)s0 * 8 + c);
        ulonglong2 v1 = __ldg(pq2 + (size_t)s1 * 8 + c);
        ulonglong2 v2 = __ldg(pq2 + (size_t)s2 * 8 + c);
        ulonglong2 v3 = __ldg(pq2 + (size_t)s3 * 8 + c);
        ADD2(a0, a0, v0.x); ADD2(a1, a1, v0.y);
        ADD2(a0, a0, v1.x); ADD2(a1, a1, v1.y);
        ADD2(a0, a0, v2.x); ADD2(a1, a1, v2.y);
        ADD2(a0, a0, v3.x); ADD2(a1, a1, v3.y);
    }
    for (; i < e; i++) {
        int s0 = __ldg(g_csr + i);
        ulonglong2 v0 = __ldg(pq2 + (size_t)s0 * 8 + c);
        ADD2(a0, a0, v0.x); ADD2(a1, a1, v0.y);
    }
    float invd = 1.f / fmaxf((float)(e - s), 1.f);
    float2 u0 = unpk2(a0), u1 = unpk2(a1);
    float4 q = nv ? __ldg((const float4*)g_pq + (size_t)node * 8 + 4 + c)
                  : make_float4(0.f, 0.f, 0.f, 0.f);
    float v[4];
    v[0] = u0.x * invd + q.x;
    v[1] = u0.y * invd + q.y;
    v[2] = u1.x * invd + q.z;
    v[3] = u1.y * invd + q.w;

    float m = fmaxf(fmaxf(v[0], v[1]), fmaxf(v[2], v[3]));
    m = fmaxf(m, __shfl_xor_sync(0xFFFFFFFFu, m, 1));
    m = fmaxf(m, __shfl_xor_sync(0xFFFFFFFFu, m, 2));
    float sum = expf(v[0] - m) + expf(v[1] - m) + expf(v[2] - m) + expf(v[3] - m);
    sum += __shfl_xor_sync(0xFFFFFFFFu, sum, 1);
    sum += __shfl_xor_sync(0xFFFFFFFFu, sum, 2);
    float lse = m + logf(sum);

    if (nv) {
        float4 o;
        o.x = v[0] - lse; o.y = v[1] - lse; o.z = v[2] - lse; o.w = v[3] - lse;
        ((float4*)out)[(size_t)node * 4 + c] = o;
    }

    // ---- reset scratch for next replay ----
    int gid = blockIdx.x * 256 + tid;
    if (gid < NN) g_cursor[gid] = 0;
    if (gid < SCAN_G) g_state[gid] = 0ull;
    if (gid == 0) g_ticket = 0;
}

// ---------------------------------------------------------------------------
extern "C" void kernel_launch(void* const* d_in, const int* in_sizes, int n_in,
                              void* d_out, int out_size) {
    const float* x   = (const float*)d_in[0];
    const int*   ei  = (const int*)d_in[1];
    const float* W1l = (const float*)d_in[2];
    const float* W1r = (const float*)d_in[3];
    const float* b1  = (const float*)d_in[4];
    const float* W2l = (const float*)d_in[5];
    const float* W2r = (const float*)d_in[6];
    const float* b2  = (const float*)d_in[7];
    float* out = (float*)d_out;

    k_hist<<<(NE + 255) / 256, 256>>>(ei);           // launch 0
    k_scan<<<SCAN_G, 512>>>();                        // 1
    k_fillgather<<<FG_BLOCKS, 256>>>(ei, x);          // 2

    cudaFuncSetAttribute(dense_kernel,
                         cudaFuncAttributeMaxDynamicSharedMemorySize,
                         DSM_FLOATS * sizeof(float));
    dense_kernel<<<(NN + 127) / 128, 128, DSM_FLOATS * sizeof(float)>>>(
        x, W1l, W1r, b1, W2l, W2r, b2);               // 3 <- profiled next round

    final_kernel<<<(NN + 63) / 64, 256>>>(out);       // 4
}